// round 10
// baseline (speedup 1.0000x reference)
#include <cuda_runtime.h>
#include <cuda_bf16.h>
#include <stdint.h>
#include <math.h>

#define BB 128
#define SS 512
#define DD 1024
#define GEN_V 50000
#define OUT_V 50257

#define NT 128                        // N columns per CTA
#define KC 32                         // K per chunk
#define NCHUNK (DD / KC)              // 32
#define NCTA ((GEN_V + NT - 1) / NT)  // 391

#define NTHREADS 320                  // 8 consumer warps + 2 producer warps

// Named barrier ids (0 reserved for __syncthreads)
#define BAR_EMPTY0 1
#define BAR_EMPTY1 2
#define BAR_FULL0  3
#define BAR_FULL1  4

// ---------------------------------------------------------------------------
// Device scratch
// ---------------------------------------------------------------------------
__device__ float   g_interp[BB];
__device__ float   g_rowsum[BB];
__device__ uint8_t g_Ahi[NCHUNK * 8192];   // pre-swizzled bf16 A, 8KB per K-chunk

// ---------------------------------------------------------------------------
// Helpers (family-safe PTX only)
// ---------------------------------------------------------------------------
__device__ __forceinline__ uint32_t smem_u32(const void* p) {
    uint32_t a;
    asm("{ .reg .u64 t; cvta.to.shared.u64 t, %1; cvt.u32.u64 %0, t; }" : "=r"(a) : "l"(p));
    return a;
}

#define BAR_SYNC(id)   asm volatile("bar.sync %0, %1;"   :: "r"(id), "r"(NTHREADS) : "memory")
#define BAR_ARRIVE(id) asm volatile("bar.arrive %0, %1;" :: "r"(id), "r"(NTHREADS) : "memory")

#define LDSM4(r, addr)                                                          \
    asm volatile("ldmatrix.sync.aligned.m8n8.x4.shared.b16 {%0,%1,%2,%3}, [%4];" \
        : "=r"((r)[0]), "=r"((r)[1]), "=r"((r)[2]), "=r"((r)[3]) : "r"(addr))

#define LDSM4T(r, addr)                                                               \
    asm volatile("ldmatrix.sync.aligned.m8n8.x4.trans.shared.b16 {%0,%1,%2,%3}, [%4];" \
        : "=r"((r)[0]), "=r"((r)[1]), "=r"((r)[2]), "=r"((r)[3]) : "r"(addr))

#define MMA_BF16(ac, a, b0, b1)                                                  \
    asm volatile("mma.sync.aligned.m16n8k16.row.col.f32.bf16.bf16.f32 "          \
        "{%0,%1,%2,%3}, {%4,%5,%6,%7}, {%8,%9}, {%0,%1,%2,%3};"                  \
        : "+f"((ac)[0]), "+f"((ac)[1]), "+f"((ac)[2]), "+f"((ac)[3])             \
        : "r"((a)[0]), "r"((a)[1]), "r"((a)[2]), "r"((a)[3]), "r"(b0), "r"(b1))

#define CPASYNC16(dst, src) \
    asm volatile("cp.async.ca.shared.global [%0], [%1], 16;" :: "r"(dst), "l"(src))
#define CPASYNC_COMMIT() asm volatile("cp.async.commit_group;")
#define CPASYNC_WAIT0()  asm volatile("cp.async.wait_group 0;" ::: "memory")

__device__ __forceinline__ uint32_t pack_bf16(float lo, float hi) {
    uint32_t r;
    asm("cvt.rn.bf16x2.f32 %0, %1, %2;" : "=r"(r) : "f"(hi), "f"(lo));
    return r;
}

// A chunk swizzle: o = m*64 + k*2, swizzled o ^ (((m>>1)&7)*16)
__device__ __host__ __forceinline__ uint32_t a_swz(int m, int k) {
    uint32_t o = (uint32_t)(m * 64 + k * 2);
    return o ^ ((((uint32_t)m >> 1) & 7u) << 4);
}

// ---------------------------------------------------------------------------
// Fused prep: blocks 0..127 gate, 128..255 prepA, 256.. zero out
// ---------------------------------------------------------------------------
__global__ void prep_kernel(const float* __restrict__ x,
                            const float* __restrict__ Wg,
                            const float* __restrict__ bg,
                            float4* __restrict__ out, int n4) {
    int blk = blockIdx.x;
    int tid = threadIdx.x;
    if (blk < BB) {
        int b = blk;
        if (tid == 0) g_rowsum[b] = 0.f;
        float s = 0.f;
        for (int d = tid; d < DD; d += 256)
            s += x[b * DD + d] * Wg[d];
        __shared__ float red[256];
        red[tid] = s;
        __syncthreads();
        for (int off = 128; off > 0; off >>= 1) {
            if (tid < off) red[tid] += red[tid + off];
            __syncthreads();
        }
        if (tid == 0)
            g_interp[b] = 1.f / (1.f + expf(-(red[0] + bg[0])));
    } else if (blk < 2 * BB) {
        int m = blk - BB;
        for (int k = tid; k < DD; k += 256) {
            float v = x[m * DD + k];
            int c = k >> 5, kk = k & 31;
            *(__nv_bfloat16*)(g_Ahi + (uint32_t)c * 8192u + a_swz(m, kk)) =
                __float2bfloat16(v);
        }
    } else {
        int i = (blk - 2 * BB) * 256 + tid;
        int stride = (gridDim.x - 2 * BB) * 256;
        for (; i < n4; i += stride) out[i] = make_float4(0.f, 0.f, 0.f, 0.f);
    }
}

// ---------------------------------------------------------------------------
// Warp-specialized bf16 GEMM: 8 consumer warps (MMA only) + 2 producer warps
// (A cp.async + B LDG/cvt/STS), named-barrier handshake, double-buffered.
// Consumer warp grid 4m x 2n, warp tile 32x64, CTA tile 128x128.
// SMEM: bias 512 | g2o 512 | A 2x8K | B 2x8K = 33.5 KB
// ---------------------------------------------------------------------------
#define OFF_G2O  512
#define OFF_A    1024
#define OFF_BBF  17408
#define SMEM_SZ  33792

__global__ __launch_bounds__(NTHREADS, 2) void gemm_mma_kernel(
    const float* __restrict__ W, const float* __restrict__ bias,
    const int* __restrict__ g2o, float* __restrict__ out)
{
    __shared__ __align__(1024) uint8_t smem[SMEM_SZ];
    const uint32_t sb = smem_u32(smem);

    const int tid = threadIdx.x;
    const int wid = tid >> 5;
    const int lid = tid & 31;
    const int n0 = blockIdx.x * NT;

    float* sBias = (float*)(smem);
    int*   sG2O  = (int*)(smem + OFF_G2O);

    if (tid < NT) {
        int gn = n0 + tid;
        bool ok = gn < GEN_V;
        sBias[tid] = ok ? bias[gn] : 0.f;
        sG2O[tid]  = ok ? g2o[gn] : 0;
    }
    __syncthreads();   // bar 0, all 320

    if (wid < 8) {
        // =================== CONSUMER ===================
        const int wm = wid >> 1;          // 0..3 (M)
        const int wn = wid & 1;           // 0..1 (N)

        float acc[2][8][4];
        #pragma unroll
        for (int i = 0; i < 2; i++)
            #pragma unroll
            for (int j = 0; j < 8; j++)
                #pragma unroll
                for (int q = 0; q < 4; q++)
                    acc[i][j][q] = 0.f;

        const int arow = wm * 32 + (lid & 15);
        const int akb  = (lid >> 4) << 4;
        const int bkrow_base = (lid & 15);
        const int bnoff = (lid >> 4) << 3;

        // Pre-arrive both EMPTY barriers so producers can fill immediately
        BAR_ARRIVE(BAR_EMPTY0);
        BAR_ARRIVE(BAR_EMPTY1);

        #pragma unroll 1
        for (int c = 0; c < NCHUNK; c++) {
            const int buf = c & 1;
            BAR_SYNC(BAR_FULL0 + buf);

            const uint32_t abuf = sb + OFF_A + buf * 8192;
            const uint32_t bbuf = sb + OFF_BBF + buf * 8192;
            #pragma unroll
            for (int ks = 0; ks < 2; ks++) {
                uint32_t ah[2][4];
                #pragma unroll
                for (int i = 0; i < 2; i++) {
                    int row = arow + i * 16;
                    uint32_t o = (uint32_t)(row * 64 + ks * 32 + akb);
                    uint32_t swz = o ^ ((((uint32_t)row >> 1) & 7u) << 4);
                    LDSM4(ah[i], abuf + swz);
                }
                #pragma unroll
                for (int j = 0; j < 4; j++) {
                    int krow = ks * 16 + bkrow_base;
                    int n = wn * 64 + j * 16 + bnoff;
                    uint32_t off = (uint32_t)krow * 256u +
                                   (((uint32_t)n * 2u) ^ (((uint32_t)krow & 7u) << 4));
                    uint32_t bh[4];
                    LDSM4T(bh, bbuf + off);
                    #pragma unroll
                    for (int i = 0; i < 2; i++) {
                        MMA_BF16(acc[i][j * 2 + 0], ah[i], bh[0], bh[1]);
                        MMA_BF16(acc[i][j * 2 + 1], ah[i], bh[2], bh[3]);
                    }
                }
            }

            BAR_ARRIVE(BAR_EMPTY0 + buf);
        }

        // ---- Epilogue: bias + exp + direct atomic scatter + rowsum ----
        #pragma unroll
        for (int i = 0; i < 2; i++) {
            int r0 = wm * 32 + i * 16 + (lid >> 2);
            int r1 = r0 + 8;
            float s0 = 0.f, s1 = 0.f;
            #pragma unroll
            for (int j = 0; j < 8; j++) {
                int cidx = wn * 64 + j * 8 + (lid & 3) * 2;
                int gn = n0 + cidx;
                if (gn < GEN_V) {
                    float b0 = sBias[cidx], b1 = sBias[cidx + 1];
                    int o0 = sG2O[cidx], o1 = sG2O[cidx + 1];
                    float p00 = __expf(acc[i][j][0] + b0);
                    float p01 = __expf(acc[i][j][1] + b1);
                    float p10 = __expf(acc[i][j][2] + b0);
                    float p11 = __expf(acc[i][j][3] + b1);
                    atomicAdd(out + (size_t)r0 * OUT_V + o0, p00);
                    atomicAdd(out + (size_t)r0 * OUT_V + o1, p01);
                    atomicAdd(out + (size_t)r1 * OUT_V + o0, p10);
                    atomicAdd(out + (size_t)r1 * OUT_V + o1, p11);
                    s0 += p00 + p01;
                    s1 += p10 + p11;
                }
            }
            s0 += __shfl_xor_sync(0xFFFFFFFF, s0, 1);
            s0 += __shfl_xor_sync(0xFFFFFFFF, s0, 2);
            s1 += __shfl_xor_sync(0xFFFFFFFF, s1, 1);
            s1 += __shfl_xor_sync(0xFFFFFFFF, s1, 2);
            if ((lid & 3) == 0) {
                atomicAdd(&g_rowsum[r0], s0);
                atomicAdd(&g_rowsum[r1], s1);
            }
        }
    } else {
        // =================== PRODUCER (warps 8,9 = 64 threads) ===================
        const int pt = (wid - 8) * 32 + lid;   // 0..63
        const int bk = pt & 31;                // k row 0..31
        const int half = pt >> 5;              // 0 or 1 -> n half (64 floats)
        const int nb = half * 64;              // n base within tile

        // validity per float4 batch element computed from global n
        const float* wrow = W + (size_t)bk * GEN_V + n0 + nb;

        #pragma unroll 1
        for (int c = 0; c < NCHUNK; c++) {
            const int buf = c & 1;
            BAR_SYNC(BAR_EMPTY0 + buf);

            // ---- A(c): 8KB via cp.async; 64 threads x 128B ----
            {
                const uint8_t* src = g_Ahi + (size_t)c * 8192 + pt * 128;
                uint32_t dst = sb + OFF_A + buf * 8192 + pt * 128;
                #pragma unroll
                for (int i = 0; i < 8; i++)
                    CPASYNC16(dst + i * 16, src + i * 128 / 8);
            }
            CPASYNC_COMMIT();

            // ---- B(c): this thread covers row bk, 64 floats at nb ----
            const float* src = wrow + (size_t)c * KC * GEN_V;
            uint32_t rowbase = sb + OFF_BBF + buf * 8192 + (uint32_t)bk * 256u;
            uint32_t kx = ((uint32_t)bk & 7u) << 4;
            #pragma unroll
            for (int batch = 0; batch < 2; batch++) {
                float4 v[8];
                #pragma unroll
                for (int i = 0; i < 8; i++) {
                    int gn = n0 + nb + batch * 32 + i * 4;
                    v[i] = (gn + 4 <= GEN_V) ? *(const float4*)(src + batch * 32 + i * 4)
                                             : make_float4(0.f, 0.f, 0.f, 0.f);
                }
                #pragma unroll
                for (int g = 0; g < 4; g++) {       // group of 8 n values
                    uint32_t u[4];
                    u[0] = pack_bf16(v[g*2].x, v[g*2].y);
                    u[1] = pack_bf16(v[g*2].z, v[g*2].w);
                    u[2] = pack_bf16(v[g*2+1].x, v[g*2+1].y);
                    u[3] = pack_bf16(v[g*2+1].z, v[g*2+1].w);
                    uint32_t n = (uint32_t)(nb + batch * 32 + g * 8);
                    uint32_t off = ((n * 2u) ^ kx);
                    *(uint4*)(smem + (rowbase - sb) + off) = *(uint4*)u;
                }
            }

            CPASYNC_WAIT0();
            BAR_ARRIVE(BAR_FULL0 + buf);
        }
    }
}

// ---------------------------------------------------------------------------
// Rescale: out[b,:] *= interp[b] / rowsum[b]  (flat float4, row per element)
// ---------------------------------------------------------------------------
__global__ void rescale_kernel(float* __restrict__ out) {
    const long n = (long)BB * OUT_V;
    const long n4 = n >> 2;
    float4* o4 = (float4*)out;
    __shared__ float sScale[BB];
    for (int b = threadIdx.x; b < BB; b += 256)
        sScale[b] = g_interp[b] / g_rowsum[b];
    __syncthreads();
    long stride = (long)gridDim.x * 256;
    for (long i = (long)blockIdx.x * 256 + threadIdx.x; i < n4; i += stride) {
        long e = i << 2;
        int b0 = (int)(e / OUT_V);
        int b3 = (int)((e + 3) / OUT_V);
        float4 v = o4[i];
        if (b0 == b3) {
            float s = sScale[b0];
            v.x *= s; v.y *= s; v.z *= s; v.w *= s;
        } else {
            v.x *= sScale[(int)((e + 0) / OUT_V)];
            v.y *= sScale[(int)((e + 1) / OUT_V)];
            v.z *= sScale[(int)((e + 2) / OUT_V)];
            v.w *= sScale[(int)((e + 3) / OUT_V)];
        }
        o4[i] = v;
    }
}

// ---------------------------------------------------------------------------
// Scatter pointer probs (after rescale)
// ---------------------------------------------------------------------------
__global__ void scatter_ptr_kernel(const float* __restrict__ alphas,
                                   const int* __restrict__ ctx,
                                   const int* __restrict__ i2o,
                                   float* __restrict__ out) {
    int b = blockIdx.y;
    int s = blockIdx.x * 256 + threadIdx.x;
    if (s >= SS) return;
    float w = (1.f - g_interp[b]) * alphas[b * SS + s];
    int o = i2o[ctx[b * SS + s]];
    atomicAdd(&out[(size_t)b * OUT_V + o], w);
}

// ---------------------------------------------------------------------------
// Launch. Inputs: x, alphas, W_gate, b_gate, W_gen, b_gen, ctx_inp,
//                 gen_to_out, inp_to_out
// ---------------------------------------------------------------------------
extern "C" void kernel_launch(void* const* d_in, const int* in_sizes, int n_in,
                              void* d_out, int out_size) {
    const float* x      = (const float*)d_in[0];
    const float* alphas = (const float*)d_in[1];
    const float* W_gate = (const float*)d_in[2];
    const float* b_gate = (const float*)d_in[3];
    const float* W_gen  = (const float*)d_in[4];
    const float* b_gen  = (const float*)d_in[5];
    const int* ctx_inp  = (const int*)d_in[6];
    const int* g2o      = (const int*)d_in[7];
    const int* i2o      = (const int*)d_in[8];
    float* out = (float*)d_out;

    prep_kernel<<<2 * BB + 1536, 256>>>(x, W_gate, b_gate,
                                        (float4*)out, (BB * OUT_V) / 4);
    gemm_mma_kernel<<<NCTA, NTHREADS>>>(W_gen, b_gen, g2o, out);
    rescale_kernel<<<1024, 256>>>(out);
    dim3 pgrid((SS + 255) / 256, BB);
    scatter_ptr_kernel<<<pgrid, 256>>>(alphas, ctx_inp, i2o, out);
}

// round 11
// speedup vs baseline: 1.4524x; 1.4524x over previous
#include <cuda_runtime.h>
#include <cuda_bf16.h>
#include <stdint.h>
#include <math.h>

#define BB 128
#define SS 512
#define DD 1024
#define GEN_V 50000
#define OUT_V 50257

#define NT 128                        // N columns per CTA
#define MT 64                         // M rows per CTA
#define KC 32                         // K per chunk
#define NCHUNK (DD / KC)              // 32
#define NNT ((GEN_V + NT - 1) / NT)   // 391 n-tiles
#define NCTA (NNT * 2)                // 782 CTAs (x2 m-halves)

// ---------------------------------------------------------------------------
// Device scratch
// ---------------------------------------------------------------------------
__device__ float   g_interp[BB];
__device__ float   g_rowsum[BB];
__device__ uint8_t g_Ahi[NCHUNK * 8192];   // pre-swizzled bf16 A, 8KB per K-chunk

// ---------------------------------------------------------------------------
// Helpers (family-safe PTX only)
// ---------------------------------------------------------------------------
__device__ __forceinline__ uint32_t smem_u32(const void* p) {
    uint32_t a;
    asm("{ .reg .u64 t; cvta.to.shared.u64 t, %1; cvt.u32.u64 %0, t; }" : "=r"(a) : "l"(p));
    return a;
}

#define LDSM4(r, addr)                                                          \
    asm volatile("ldmatrix.sync.aligned.m8n8.x4.shared.b16 {%0,%1,%2,%3}, [%4];" \
        : "=r"((r)[0]), "=r"((r)[1]), "=r"((r)[2]), "=r"((r)[3]) : "r"(addr))

#define LDSM4T(r, addr)                                                               \
    asm volatile("ldmatrix.sync.aligned.m8n8.x4.trans.shared.b16 {%0,%1,%2,%3}, [%4];" \
        : "=r"((r)[0]), "=r"((r)[1]), "=r"((r)[2]), "=r"((r)[3]) : "r"(addr))

#define MMA_BF16(ac, a, b0, b1)                                                  \
    asm volatile("mma.sync.aligned.m16n8k16.row.col.f32.bf16.bf16.f32 "          \
        "{%0,%1,%2,%3}, {%4,%5,%6,%7}, {%8,%9}, {%0,%1,%2,%3};"                  \
        : "+f"((ac)[0]), "+f"((ac)[1]), "+f"((ac)[2]), "+f"((ac)[3])             \
        : "r"((a)[0]), "r"((a)[1]), "r"((a)[2]), "r"((a)[3]), "r"(b0), "r"(b1))

#define CPASYNC16(dst, src) \
    asm volatile("cp.async.ca.shared.global [%0], [%1], 16;" :: "r"(dst), "l"(src))
#define CPASYNC_COMMIT() asm volatile("cp.async.commit_group;")
#define CPASYNC_WAIT1()  asm volatile("cp.async.wait_group 1;" ::: "memory")

__device__ __forceinline__ uint32_t pack_bf16(float lo, float hi) {
    uint32_t r;
    asm("cvt.rn.bf16x2.f32 %0, %1, %2;" : "=r"(r) : "f"(hi), "f"(lo));
    return r;
}

// A chunk swizzle: o = m*64 + k*2, swizzled o ^ (((m>>1)&7)*16)
// XOR touches bits 4..6 only -> stays within the (m&~1, m|1) row pair, so a
// 64-row half [mb*64, mb*64+64) occupies exactly bytes [mb*4096, mb*4096+4096).
__device__ __host__ __forceinline__ uint32_t a_swz(int m, int k) {
    uint32_t o = (uint32_t)(m * 64 + k * 2);
    return o ^ ((((uint32_t)m >> 1) & 7u) << 4);
}

// ---------------------------------------------------------------------------
// Fused prep: blocks 0..127 gate, 128..255 prepA, 256.. zero out
// ---------------------------------------------------------------------------
__global__ void prep_kernel(const float* __restrict__ x,
                            const float* __restrict__ Wg,
                            const float* __restrict__ bg,
                            float4* __restrict__ out, int n4) {
    int blk = blockIdx.x;
    int tid = threadIdx.x;
    if (blk < BB) {
        int b = blk;
        if (tid == 0) g_rowsum[b] = 0.f;
        float s = 0.f;
        for (int d = tid; d < DD; d += 256)
            s += x[b * DD + d] * Wg[d];
        __shared__ float red[256];
        red[tid] = s;
        __syncthreads();
        for (int off = 128; off > 0; off >>= 1) {
            if (tid < off) red[tid] += red[tid + off];
            __syncthreads();
        }
        if (tid == 0)
            g_interp[b] = 1.f / (1.f + expf(-(red[0] + bg[0])));
    } else if (blk < 2 * BB) {
        int m = blk - BB;
        for (int k = tid; k < DD; k += 256) {
            float v = x[m * DD + k];
            int c = k >> 5, kk = k & 31;
            *(__nv_bfloat16*)(g_Ahi + (uint32_t)c * 8192u + a_swz(m, kk)) =
                __float2bfloat16(v);
        }
    } else {
        int i = (blk - 2 * BB) * 256 + tid;
        int stride = (gridDim.x - 2 * BB) * 256;
        for (; i < n4; i += stride) out[i] = make_float4(0.f, 0.f, 0.f, 0.f);
    }
}

// ---------------------------------------------------------------------------
// Pure-bf16 GEMM (mma.sync). CTA tile 64(m) x 128(n), 128 threads, warp grid
// 2m x 2n, warp tile 32x64 (same per-warp hot loop as the 123us version).
// 4 CTAs/SM for decorrelated pipelines. Single-barrier pipelined chunks,
// hoisted staging, fused exp + atomic scatter epilogue.
// SMEM: bias 512 | g2o 512 | A ring 3x4K | B 2x8K = 29 KB
// ---------------------------------------------------------------------------
#define OFF_G2O  512
#define OFF_A    1024
#define OFF_BBF  13312
#define SMEM_SZ  29696

__global__ __launch_bounds__(128, 4) void gemm_mma_kernel(
    const float* __restrict__ W, const float* __restrict__ bias,
    const int* __restrict__ g2o, float* __restrict__ out)
{
    __shared__ __align__(1024) uint8_t smem[SMEM_SZ];
    const uint32_t sb = smem_u32(smem);

    const int tid = threadIdx.x;
    const int wid = tid >> 5;
    const int lid = tid & 31;
    const int wm = wid >> 1;          // 0..1 (M)
    const int wn = wid & 1;           // 0..1 (N)
    const int n0 = (blockIdx.x >> 1) * NT;
    const int mb = blockIdx.x & 1;    // m half: rows mb*64..mb*64+63
    const int m0 = mb * MT;

    float* sBias = (float*)(smem);
    int*   sG2O  = (int*)(smem + OFF_G2O);

    {
        int gn = n0 + tid;
        bool ok = gn < GEN_V;
        sBias[tid] = ok ? bias[gn] : 0.f;
        sG2O[tid]  = ok ? g2o[gn] : 0;
    }

    // ---- B loader: 4 k-rows (bk, bk+8, bk+16, bk+24) x 8 n per thread ----
    const int bk = tid >> 4;            // 0..7
    const int ng = (tid & 15) * 8;      // n offset (0..120)
    const bool bok = (n0 + ng) < GEN_V;
    const uint32_t kx = ((uint32_t)bk & 7u) << 4;   // swizzle const (bk+8r keeps low 3 bits)

    float4 pf[8];   // row r: pf[2r], pf[2r+1]

    auto loadB = [&](int c) {
        #pragma unroll
        for (int r = 0; r < 4; r++) {
            const float* p = W + (size_t)(c * KC + bk + r * 8) * GEN_V + n0 + ng;
            if (bok) {
                pf[2 * r]     = *(const float4*)(p);
                pf[2 * r + 1] = *(const float4*)(p + 4);
            } else {
                pf[2 * r] = pf[2 * r + 1] = make_float4(0.f, 0.f, 0.f, 0.f);
            }
        }
    };

    auto storeB = [&](int buf) {
        #pragma unroll
        for (int r = 0; r < 4; r++) {
            int k = bk + r * 8;
            float4 a = pf[2 * r], b4 = pf[2 * r + 1];
            uint32_t u[4];
            u[0] = pack_bf16(a.x, a.y);
            u[1] = pack_bf16(a.z, a.w);
            u[2] = pack_bf16(b4.x, b4.y);
            u[3] = pack_bf16(b4.z, b4.w);
            uint32_t off = (uint32_t)k * 256u + (((uint32_t)ng * 2u) ^ kx);
            *(uint4*)(smem + OFF_BBF + buf * 8192 + off) = *(uint4*)u;
        }
    };

    auto loadA_async = [&](int c) {
        const uint8_t* src = g_Ahi + (size_t)c * 8192 + mb * 4096 + tid * 32;
        uint32_t dst = sb + OFF_A + (c % 3) * 4096 + tid * 32;
        CPASYNC16(dst, src);
        CPASYNC16(dst + 16, src + 16);
    };

    float acc[2][8][4];
    #pragma unroll
    for (int i = 0; i < 2; i++)
        #pragma unroll
        for (int j = 0; j < 8; j++)
            #pragma unroll
            for (int q = 0; q < 4; q++)
                acc[i][j][q] = 0.f;

    // ldmatrix lane address components (A rows are global; slice base folded below)
    const int arow = m0 + wm * 32 + (lid & 15);
    const int akb  = (lid >> 4) << 4;
    const int bkrow_base = (lid & 15);
    const int bnoff = (lid >> 4) << 3;
    const uint32_t a_slice_sub = (uint32_t)(mb * 4096);

    // ---- Prologue ----
    loadA_async(0); CPASYNC_COMMIT();      // group A0
    loadA_async(1); CPASYNC_COMMIT();      // group A1
    loadB(0);
    storeB(0);                              // buf0 = B(0)
    loadB(1);                               // pf = B(1)
    CPASYNC_WAIT1();                        // A0 done, A1 flying
    __syncthreads();

    #pragma unroll 1
    for (int c = 0; c < NCHUNK; c++) {
        // ---- Hoisted staging ----
        if (c + 1 < NCHUNK) {
            storeB((c + 1) & 1);            // consumes pf (chunk c+1)
            if (c + 2 < NCHUNK)
                loadB(c + 2);               // LDG -> pf, covered by MMA(c)
        }

        // ---- MMA over chunk c ----
        const uint32_t abuf = sb + OFF_A + (c % 3) * 4096 - a_slice_sub;
        const uint32_t bbuf = sb + OFF_BBF + (c & 1) * 8192;
        #pragma unroll
        for (int ks = 0; ks < 2; ks++) {
            uint32_t ah[2][4];
            #pragma unroll
            for (int i = 0; i < 2; i++) {
                int row = arow + i * 16;
                uint32_t o = (uint32_t)(row * 64 + ks * 32 + akb);
                uint32_t swz = o ^ ((((uint32_t)row >> 1) & 7u) << 4);
                LDSM4(ah[i], abuf + swz);
            }
            #pragma unroll
            for (int j = 0; j < 4; j++) {
                int krow = ks * 16 + bkrow_base;
                int n = wn * 64 + j * 16 + bnoff;
                uint32_t off = (uint32_t)krow * 256u +
                               (((uint32_t)n * 2u) ^ (((uint32_t)krow & 7u) << 4));
                uint32_t bh[4];
                LDSM4T(bh, bbuf + off);
                #pragma unroll
                for (int i = 0; i < 2; i++) {
                    MMA_BF16(acc[i][j * 2 + 0], ah[i], bh[0], bh[1]);
                    MMA_BF16(acc[i][j * 2 + 1], ah[i], bh[2], bh[3]);
                }
            }
        }

        // ---- Post-MMA: A prefetch + wait + single barrier ----
        if (c + 1 < NCHUNK) {
            if (c + 2 < NCHUNK)
                loadA_async(c + 2);         // -> slot (c+2)%3
            CPASYNC_COMMIT();
            CPASYNC_WAIT1();                // A(c+1) done
            __syncthreads();
        }
    }

    // ---- Epilogue: bias + exp + direct atomic scatter + rowsum ----
    #pragma unroll
    for (int i = 0; i < 2; i++) {
        int r0 = m0 + wm * 32 + i * 16 + (lid >> 2);
        int r1 = r0 + 8;
        float s0 = 0.f, s1 = 0.f;
        #pragma unroll
        for (int j = 0; j < 8; j++) {
            int cidx = wn * 64 + j * 8 + (lid & 3) * 2;
            int gn = n0 + cidx;
            if (gn < GEN_V) {
                float b0 = sBias[cidx], b1 = sBias[cidx + 1];
                int o0 = sG2O[cidx], o1 = sG2O[cidx + 1];
                float p00 = __expf(acc[i][j][0] + b0);
                float p01 = __expf(acc[i][j][1] + b1);
                float p10 = __expf(acc[i][j][2] + b0);
                float p11 = __expf(acc[i][j][3] + b1);
                atomicAdd(out + (size_t)r0 * OUT_V + o0, p00);
                atomicAdd(out + (size_t)r0 * OUT_V + o1, p01);
                atomicAdd(out + (size_t)r1 * OUT_V + o0, p10);
                atomicAdd(out + (size_t)r1 * OUT_V + o1, p11);
                s0 += p00 + p01;
                s1 += p10 + p11;
            }
        }
        s0 += __shfl_xor_sync(0xFFFFFFFF, s0, 1);
        s0 += __shfl_xor_sync(0xFFFFFFFF, s0, 2);
        s1 += __shfl_xor_sync(0xFFFFFFFF, s1, 1);
        s1 += __shfl_xor_sync(0xFFFFFFFF, s1, 2);
        if ((lid & 3) == 0) {
            atomicAdd(&g_rowsum[r0], s0);
            atomicAdd(&g_rowsum[r1], s1);
        }
    }
}

// ---------------------------------------------------------------------------
// Rescale: out[b,:] *= interp[b] / rowsum[b]  (flat float4, row per element)
// ---------------------------------------------------------------------------
__global__ void rescale_kernel(float* __restrict__ out) {
    const long n = (long)BB * OUT_V;
    const long n4 = n >> 2;
    float4* o4 = (float4*)out;
    __shared__ float sScale[BB];
    for (int b = threadIdx.x; b < BB; b += 256)
        sScale[b] = g_interp[b] / g_rowsum[b];
    __syncthreads();
    long stride = (long)gridDim.x * 256;
    for (long i = (long)blockIdx.x * 256 + threadIdx.x; i < n4; i += stride) {
        long e = i << 2;
        int b0 = (int)(e / OUT_V);
        int b3 = (int)((e + 3) / OUT_V);
        float4 v = o4[i];
        if (b0 == b3) {
            float s = sScale[b0];
            v.x *= s; v.y *= s; v.z *= s; v.w *= s;
        } else {
            v.x *= sScale[(int)((e + 0) / OUT_V)];
            v.y *= sScale[(int)((e + 1) / OUT_V)];
            v.z *= sScale[(int)((e + 2) / OUT_V)];
            v.w *= sScale[(int)((e + 3) / OUT_V)];
        }
        o4[i] = v;
    }
}

// ---------------------------------------------------------------------------
// Scatter pointer probs (after rescale)
// ---------------------------------------------------------------------------
__global__ void scatter_ptr_kernel(const float* __restrict__ alphas,
                                   const int* __restrict__ ctx,
                                   const int* __restrict__ i2o,
                                   float* __restrict__ out) {
    int b = blockIdx.y;
    int s = blockIdx.x * 256 + threadIdx.x;
    if (s >= SS) return;
    float w = (1.f - g_interp[b]) * alphas[b * SS + s];
    int o = i2o[ctx[b * SS + s]];
    atomicAdd(&out[(size_t)b * OUT_V + o], w);
}

// ---------------------------------------------------------------------------
// Launch. Inputs: x, alphas, W_gate, b_gate, W_gen, b_gen, ctx_inp,
//                 gen_to_out, inp_to_out
// ---------------------------------------------------------------------------
extern "C" void kernel_launch(void* const* d_in, const int* in_sizes, int n_in,
                              void* d_out, int out_size) {
    const float* x      = (const float*)d_in[0];
    const float* alphas = (const float*)d_in[1];
    const float* W_gate = (const float*)d_in[2];
    const float* b_gate = (const float*)d_in[3];
    const float* W_gen  = (const float*)d_in[4];
    const float* b_gen  = (const float*)d_in[5];
    const int* ctx_inp  = (const int*)d_in[6];
    const int* g2o      = (const int*)d_in[7];
    const int* i2o      = (const int*)d_in[8];
    float* out = (float*)d_out;

    prep_kernel<<<2 * BB + 1536, 256>>>(x, W_gate, b_gate,
                                        (float4*)out, (BB * OUT_V) / 4);
    gemm_mma_kernel<<<NCTA, 128>>>(W_gen, b_gen, g2o, out);
    rescale_kernel<<<1024, 256>>>(out);
    dim3 pgrid((SS + 255) / 256, BB);
    scatter_ptr_kernel<<<pgrid, 256>>>(alphas, ctx_inp, i2o, out);
}